// round 13
// baseline (speedup 1.0000x reference)
#include <cuda_runtime.h>
#include <cuda_bf16.h>
#include <cuda_fp16.h>
#include <stdint.h>

#define BATCH 64
#define SEQ   512
#define IDIM  1024
#define HDIM  1024
#define G4    4096
#define M_TOTAL (BATCH*SEQ)

// ---------------- scratch (no cudaMalloc allowed) ----------------
__device__ float g_xg[(size_t)M_TOTAL * G4];
__device__ __align__(16) __half g_xh[(size_t)M_TOTAL * IDIM];   // x fp16
__device__ __align__(16) __half g_Wihf[(size_t)G4 * IDIM];      // W_ih fp16
__device__ __align__(16) __half g_Wf[(size_t)G4 * HDIM];        // rearranged W_hh fp16
__device__ __align__(16) __half g_hh[2][BATCH * HDIM];          // h state fp16 (ping-pong)
__device__ unsigned g_ck[4 * 32];                               // per-chunk flags (128B apart)

// ---------------- PTX helpers (base compute_103-safe) ----------------
__device__ __forceinline__ uint32_t smem_u32(const void* p) {
    return (uint32_t)__cvta_generic_to_shared(p);
}
__device__ __forceinline__ void ldmx4(uint32_t r[4], uint32_t addr) {
    asm volatile("ldmatrix.sync.aligned.m8n8.x4.shared.b16 {%0,%1,%2,%3}, [%4];"
        : "=r"(r[0]), "=r"(r[1]), "=r"(r[2]), "=r"(r[3]) : "r"(addr));
}
__device__ __forceinline__ void mma_f16(float c[4], const uint32_t a[4],
                                        uint32_t b0, uint32_t b1) {
    asm volatile("mma.sync.aligned.m16n8k16.row.col.f32.f16.f16.f32 "
        "{%0,%1,%2,%3}, {%4,%5,%6,%7}, {%8,%9}, {%0,%1,%2,%3};"
        : "+f"(c[0]), "+f"(c[1]), "+f"(c[2]), "+f"(c[3])
        : "r"(a[0]), "r"(a[1]), "r"(a[2]), "r"(a[3]), "r"(b0), "r"(b1));
}
__device__ __forceinline__ void cp16(uint32_t dst, const void* src) {
    asm volatile("cp.async.cg.shared.global [%0], [%1], 16;" :: "r"(dst), "l"(src));
}
#define CP_COMMIT() asm volatile("cp.async.commit_group;" ::: "memory")
#define CP_WAIT1()  asm volatile("cp.async.wait_group 1;" ::: "memory")
#define CP_WAIT0()  asm volatile("cp.async.wait_group 0;" ::: "memory")

__device__ __forceinline__ unsigned ld_acq(const unsigned* p) {
    unsigned v;
    asm volatile("ld.acquire.gpu.u32 %0, [%1];" : "=r"(v) : "l"(p) : "memory");
    return v;
}
__device__ __forceinline__ void red_release(unsigned* p, unsigned v) {
    asm volatile("red.add.release.gpu.global.u32 [%0], %1;" :: "l"(p), "r"(v) : "memory");
}

// ---------------- MUFU-free activations ----------------
__device__ __forceinline__ float fast_rcp(float q) {
    float r = __uint_as_float(0x7EF311C2u - __float_as_uint(q));
    r = r * (2.0f - q * r);
    r = r * (2.0f - q * r);
    r = r * (2.0f - q * r);
    return r;
}
__device__ __forceinline__ float fast_tanh(float x) {
    x = fminf(fmaxf(x, -7.90531110763549805f), 7.90531110763549805f);
    float s = x * x;
    float p = fmaf(s, -2.76076847742355e-16f, 2.00018790482477e-13f);
    p = fmaf(p, s, -8.60467152213735e-11f);
    p = fmaf(p, s,  5.12229709037114e-08f);
    p = fmaf(p, s,  1.48572235717979e-05f);
    p = fmaf(p, s,  6.37261928875436e-04f);
    p = fmaf(p, s,  4.89352455891786e-03f);
    p = x * p;
    float q = fmaf(s, 1.19825839466702e-06f, 1.18534705686654e-04f);
    q = fmaf(q, s, 2.26843463243900e-03f);
    q = fmaf(q, s, 4.89352518554385e-03f);
    return p * fast_rcp(q);
}
__device__ __forceinline__ float fast_sigmoid(float x) {
    return fmaf(fast_tanh(0.5f * x), 0.5f, 0.5f);
}

// ---------------- fused setup: init state + all fp16 converts ----------------
// Single kernel -> kernel_launch is exactly 3 launches (setup, gemm, persistent)
// so ncu's "-s 5 -c 1" lands on lstm_persistent.
__global__ void setup_kernel(const float* __restrict__ x,
                             const float* __restrict__ Wih,
                             const float* __restrict__ Whh) {
    const size_t stride = (size_t)gridDim.x * blockDim.x;
    const size_t t0 = (size_t)blockIdx.x * blockDim.x + threadIdx.x;

    for (size_t i = t0; i < 4 * 32; i += stride) g_ck[i] = 0u;
    for (size_t i = t0; i < (size_t)BATCH * HDIM; i += stride) {
        __half z = __float2half(0.f);
        g_hh[0][i] = z; g_hh[1][i] = z;
    }
    for (size_t i = t0; i < (size_t)G4 * IDIM; i += stride)
        g_Wihf[i] = __float2half(Wih[i]);
    // W_hh rearrange: out_row = blk*32 + g*8 + hl <- in_row = g*1024 + blk*8 + hl
    for (size_t i = t0; i < (size_t)G4 * HDIM; i += stride) {
        int out_row = (int)(i >> 10);
        int k   = (int)(i & 1023);
        int blk = out_row >> 5;
        int lg  = out_row & 31;
        int in_row = (lg >> 3) * HDIM + blk * 8 + (lg & 7);
        g_Wf[i] = __float2half(Whh[(size_t)in_row * HDIM + k]);
    }
    for (size_t i = t0; i < (size_t)M_TOTAL * IDIM; i += stride)
        g_xh[i] = __float2half(x[i]);
}

// ---------------- input projection GEMM (plain fp16 HMMA) ----------------
// xg[m][n] = x[m][:] . Wih[n][:] + bih[n]+bhh[n]; block 128x128, K-chunk 32.
#define GI_A     0
#define GI_B     10240
#define GI_STAGE 20480
#define GI_SMEM  (3*GI_STAGE)     // 61440

__global__ void __launch_bounds__(256, 1)
gemm_input_tc(const float* __restrict__ bih, const float* __restrict__ bhh) {
    extern __shared__ char smem[];
    const uint32_t sb = smem_u32(smem);
    const int tid = threadIdx.x, wid = tid >> 5, lane = tid & 31;
    const int mbase = blockIdx.x * 128;
    const int nbase = blockIdx.y * 128;
    const int wm = wid & 1, wn = wid >> 1;

    float acc[4][4][4] = {};

#define GI_ISSUE(i) do {                                                      \
    uint32_t st = sb + ((i) % 3) * GI_STAGE;                                  \
    _Pragma("unroll")                                                         \
    for (int p = 0; p < 2; p++) {                                             \
        int u = tid + p * 256; int r = u >> 2, c = u & 3;                     \
        size_t g = (size_t)(mbase + r) * IDIM + (size_t)(i) * 32 + c * 8;     \
        cp16(st + GI_A + r * 80 + c * 16, g_xh + g);                          \
    }                                                                         \
    _Pragma("unroll")                                                         \
    for (int p = 0; p < 2; p++) {                                             \
        int u = tid + p * 256; int r = u >> 2, c = u & 3;                     \
        size_t g = (size_t)(nbase + r) * IDIM + (size_t)(i) * 32 + c * 8;     \
        cp16(st + GI_B + r * 80 + c * 16, g_Wihf + g);                        \
    }                                                                         \
} while (0)

    GI_ISSUE(0); CP_COMMIT();
    GI_ISSUE(1); CP_COMMIT();

    for (int i = 0; i < 32; i++) {
        CP_WAIT1();
        __syncthreads();
        if (i + 2 < 32) GI_ISSUE(i + 2);
        CP_COMMIT();

        uint32_t st = sb + (i % 3) * GI_STAGE;
#pragma unroll
        for (int kk = 0; kk < 2; kk++) {
            const int colb = kk * 16 + ((lane >> 4) << 3);
            uint32_t a[4][4], b[2][4];
#pragma unroll
            for (int mt = 0; mt < 4; mt++) {
                int row = wm * 64 + mt * 16 + (lane & 15);
                ldmx4(a[mt], st + GI_A + row * 80 + colb * 2);
            }
#pragma unroll
            for (int bt = 0; bt < 2; bt++) {
                int row = wn * 32 + bt * 16 + (lane & 15);
                ldmx4(b[bt], st + GI_B + row * 80 + colb * 2);
            }
#pragma unroll
            for (int mt = 0; mt < 4; mt++)
#pragma unroll
                for (int nt = 0; nt < 4; nt++) {
                    int bt = nt >> 1, ns = nt & 1;
                    mma_f16(acc[mt][nt], a[mt], b[bt][ns], b[bt][ns + 2]);
                }
        }
    }

#pragma unroll
    for (int mt = 0; mt < 4; mt++) {
        int m0 = mbase + wm * 64 + mt * 16 + (lane >> 2);
#pragma unroll
        for (int nt = 0; nt < 4; nt++) {
            int n = nbase + wn * 32 + nt * 8 + (lane & 3) * 2;
            float b0 = bih[n] + bhh[n];
            float b1 = bih[n + 1] + bhh[n + 1];
            __stcs((float2*)(g_xg + (size_t)m0 * G4 + n),
                   make_float2(acc[mt][nt][0] + b0, acc[mt][nt][1] + b1));
            __stcs((float2*)(g_xg + (size_t)(m0 + 8) * G4 + n),
                   make_float2(acc[mt][nt][2] + b0, acc[mt][nt][3] + b1));
        }
    }
}

// ---------------- persistent LSTM step kernel (fp16, flag dataflow) --------
// R10 structure (3-stage incremental pipeline) + per-warp flag posting:
// each warp red.release's after __syncwarp() (its own h stores ordered),
// consumer target = 512*t. Removes the final __syncthreads from the
// inter-block critical chain; warp 0 enters the next flag wait early.
#define PS_W      0
#define PS_WCH    16896                  // 32 rows * 528B per chunk
#define PS_H      67584                  // 4 * PS_WCH
#define PS_HSTAGE 33792                  // 64 rows * 528B
#define PS_SG     (PS_H + 3*PS_HSTAGE)   // 168960 (dedicated gate-exchange)
#define PS_SMEM   (PS_SG + 4*2176*4)     // 203776

__global__ void __launch_bounds__(512, 1)
lstm_persistent(float* __restrict__ Hout, float* __restrict__ Cout) {
    extern __shared__ char smem[];
    const uint32_t sb = smem_u32(smem);
    const int tid = threadIdx.x, wid = tid >> 5, lane = tid & 31;
    const int blk = blockIdx.x;
    const int wm = wid & 1;            // M half (16 rows)
    const int wn = (wid >> 1) & 1;     // N half (32 batches)
    const int kw = wid >> 2;           // K quarter of chunk (64)
    const int myck = blk >> 5;         // chunk this block produces

    // ---- preload W slice fp16: 4 chunks x 32 rows x 256 k ----
#pragma unroll
    for (int p = 0; p < 8; p++) {
        int u = tid + p * 512;
        int ch = u >> 10, r = (u >> 5) & 31, c = u & 31;
        size_t g = (size_t)(blk * 32 + r) * HDIM + ch * 256 + c * 8;
        cp16(sb + PS_W + ch * PS_WCH + r * 528 + c * 16, g_Wf + g);
    }
    CP_COMMIT();
    CP_WAIT0();
    __syncthreads();

    float* sg = (float*)(smem + PS_SG);   // [4 kw][32 rows][68], dedicated

    const int hl = tid & 7;
    const int bcell = tid >> 3;
    const int hcol = blk * 8 + hl;
    float creg = 0.f;

    float xgi, xgf, xgg, xgo;
    {
        size_t xb = ((size_t)bcell * SEQ + 0) * G4 + hcol;
        xgi = __ldcs(g_xg + xb);
        xgf = __ldcs(g_xg + xb + 1024);
        xgg = __ldcs(g_xg + xb + 2048);
        xgo = __ldcs(g_xg + xb + 3072);
    }

    for (int t = 0; t < SEQ; t++) {
        const int pin = t & 1, pout = pin ^ 1;
        const __half* hhp = g_hh[pin];

        // ---- consolidated flag wait: all 4 chunks ready before pipeline ----
        // (per-warp posting: 16 warps x 32 blocks = 512 posts per chunk/step)
        if (tid < 4) {
            const unsigned tgt = 512u * (unsigned)t;
            const unsigned* fp = &g_ck[tid * 32];
            while (ld_acq(fp) < tgt) {}
        }
        __syncthreads();

        float acc[4][4] = {};

#define PS_ISSUE(i) do {                                                     \
    uint32_t st = sb + PS_H + ((i) % 3) * PS_HSTAGE;                         \
    _Pragma("unroll")                                                        \
    for (int p = 0; p < 4; p++) {                                            \
        int u = tid + p * 512; int r = u >> 5, c = u & 31;                   \
        size_t g = (size_t)r * HDIM + (size_t)(i) * 256 + c * 8;             \
        cp16(st + r * 528 + c * 16, hhp + g);                                \
    }                                                                        \
} while (0)

        PS_ISSUE(0); CP_COMMIT();
        PS_ISSUE(1); CP_COMMIT();

        for (int i = 0; i < 4; i++) {
            CP_WAIT1();
            __syncthreads();
            if (i + 2 < 4) PS_ISSUE(i + 2);
            CP_COMMIT();

            uint32_t hstg  = sb + PS_H + (i % 3) * PS_HSTAGE;
            uint32_t wbase = sb + PS_W + i * PS_WCH;

            uint32_t b[2][4][4];   // [nb(16 batches)][kk(k16)]
#pragma unroll
            for (int nb = 0; nb < 2; nb++)
#pragma unroll
                for (int kk = 0; kk < 4; kk++)
                    ldmx4(b[nb][kk],
                          hstg + (wn * 32 + nb * 16 + (lane & 15)) * 528
                               + (kw * 64 + kk * 16 + (lane >> 4) * 8) * 2);
#pragma unroll
            for (int kk = 0; kk < 4; kk++) {
                uint32_t a[4];
                ldmx4(a, wbase + (wm * 16 + (lane & 15)) * 528
                              + (kw * 64 + kk * 16 + (lane >> 4) * 8) * 2);
#pragma unroll
                for (int nb = 0; nb < 2; nb++)
#pragma unroll
                    for (int ns = 0; ns < 2; ns++)
                        mma_f16(acc[nb * 2 + ns], a, b[nb][kk][ns], b[nb][kk][ns + 2]);
            }
        }

        // gate exchange (dedicated sg: no WAR with stages)
        {
            int row = wm * 16 + (lane >> 2);
            float* base = sg + kw * 2176;
#pragma unroll
            for (int nb = 0; nb < 2; nb++)
#pragma unroll
                for (int ns = 0; ns < 2; ns++) {
                    int ai = nb * 2 + ns;
                    int col = wn * 32 + nb * 16 + ns * 8 + (lane & 3) * 2;
                    base[row * 68 + col]           = acc[ai][0];
                    base[row * 68 + col + 1]       = acc[ai][1];
                    base[(row + 8) * 68 + col]     = acc[ai][2];
                    base[(row + 8) * 68 + col + 1] = acc[ai][3];
                }
        }
        __syncthreads();

        // cell update (1 cell/thread, c in register); sum 4 kw partials
        float hnew, cnew;
        {
            float gi = xgi, gf = xgf, gg = xgg, go = xgo;
#pragma unroll
            for (int k = 0; k < 4; k++) {
                const float* base = sg + k * 2176;
                gi += base[(0 * 8 + hl) * 68 + bcell];
                gf += base[(1 * 8 + hl) * 68 + bcell];
                gg += base[(2 * 8 + hl) * 68 + bcell];
                go += base[(3 * 8 + hl) * 68 + bcell];
            }

            float iv = fast_sigmoid(gi);
            float fv = fast_sigmoid(gf);
            float gv = fast_tanh(gg);
            float ov = fast_sigmoid(go);

            cnew = fv * creg + iv * gv;
            hnew = ov * fast_tanh(cnew);
            creg = cnew;

            g_hh[pout][bcell * HDIM + hcol] = __float2half(hnew);
        }

        // per-warp flag post: this warp's h stores ordered by syncwarp +
        // release; consumers count 512 posts per chunk per step.
        __syncwarp();
        if (lane == 0 && t + 1 < SEQ) red_release(&g_ck[myck * 32], 1u);

        // outputs + xg prefetch off the inter-block critical path
        size_t oidx = ((size_t)bcell * SEQ + t) * HDIM + hcol;
        __stcs(Hout + oidx, hnew);
        __stcs(Cout + oidx, cnew);

        if (t + 1 < SEQ) {
            size_t xb = ((size_t)bcell * SEQ + (t + 1)) * G4 + hcol;
            xgi = __ldcs(g_xg + xb);
            xgf = __ldcs(g_xg + xb + 1024);
            xgg = __ldcs(g_xg + xb + 2048);
            xgo = __ldcs(g_xg + xb + 3072);
        }
        // next iteration's top __syncthreads orders sg reads vs re-writes
    }
}

// ---------------- launch ----------------
extern "C" void kernel_launch(void* const* d_in, const int* in_sizes, int n_in,
                              void* d_out, int out_size) {
    const float* x    = (const float*)d_in[0];
    const float* Wih  = (const float*)d_in[1];
    const float* Whh  = (const float*)d_in[2];
    const float* bih  = (const float*)d_in[3];
    const float* bhh  = (const float*)d_in[4];

    float* Hout = (float*)d_out;
    float* Cout = Hout + (size_t)BATCH * SEQ * HDIM;

    cudaFuncSetAttribute(gemm_input_tc,   cudaFuncAttributeMaxDynamicSharedMemorySize, GI_SMEM);
    cudaFuncSetAttribute(lstm_persistent, cudaFuncAttributeMaxDynamicSharedMemorySize, PS_SMEM);

    setup_kernel<<<1184, 256>>>(x, Wih, Whh);

    dim3 g1(M_TOTAL / 128, G4 / 128);   // 256 x 32
    gemm_input_tc<<<g1, 256, GI_SMEM>>>(bih, bhh);

    lstm_persistent<<<128, 512, PS_SMEM>>>(Hout, Cout);
}

// round 14
// speedup vs baseline: 1.0582x; 1.0582x over previous
#include <cuda_runtime.h>
#include <cuda_bf16.h>
#include <cuda_fp16.h>
#include <stdint.h>

#define BATCH 64
#define SEQ   512
#define IDIM  1024
#define HDIM  1024
#define G4    4096
#define M_TOTAL (BATCH*SEQ)

// ---------------- scratch (no cudaMalloc allowed) ----------------
__device__ float g_xg[(size_t)M_TOTAL * G4];
__device__ __align__(16) __half g_xh[(size_t)M_TOTAL * IDIM];   // x fp16
__device__ __align__(16) __half g_Wihf[(size_t)G4 * IDIM];      // W_ih fp16
__device__ __align__(16) __half g_Wf[(size_t)G4 * HDIM];        // rearranged W_hh fp16
__device__ __align__(16) __half g_hh[2][BATCH * HDIM];          // h state fp16 (ping-pong)
__device__ unsigned g_ck[4 * 32];                               // per-chunk flags (128B apart)

// ---------------- PTX helpers (base compute_103-safe) ----------------
__device__ __forceinline__ uint32_t smem_u32(const void* p) {
    return (uint32_t)__cvta_generic_to_shared(p);
}
__device__ __forceinline__ void ldmx4(uint32_t r[4], uint32_t addr) {
    asm volatile("ldmatrix.sync.aligned.m8n8.x4.shared.b16 {%0,%1,%2,%3}, [%4];"
        : "=r"(r[0]), "=r"(r[1]), "=r"(r[2]), "=r"(r[3]) : "r"(addr));
}
__device__ __forceinline__ void mma_f16(float c[4], const uint32_t a[4],
                                        uint32_t b0, uint32_t b1) {
    asm volatile("mma.sync.aligned.m16n8k16.row.col.f32.f16.f16.f32 "
        "{%0,%1,%2,%3}, {%4,%5,%6,%7}, {%8,%9}, {%0,%1,%2,%3};"
        : "+f"(c[0]), "+f"(c[1]), "+f"(c[2]), "+f"(c[3])
        : "r"(a[0]), "r"(a[1]), "r"(a[2]), "r"(a[3]), "r"(b0), "r"(b1));
}
__device__ __forceinline__ void cp16(uint32_t dst, const void* src) {
    asm volatile("cp.async.cg.shared.global [%0], [%1], 16;" :: "r"(dst), "l"(src));
}
#define CP_COMMIT() asm volatile("cp.async.commit_group;" ::: "memory")
#define CP_WAIT1()  asm volatile("cp.async.wait_group 1;" ::: "memory")
#define CP_WAIT0()  asm volatile("cp.async.wait_group 0;" ::: "memory")

__device__ __forceinline__ unsigned ld_acq(const unsigned* p) {
    unsigned v;
    asm volatile("ld.acquire.gpu.u32 %0, [%1];" : "=r"(v) : "l"(p) : "memory");
    return v;
}
__device__ __forceinline__ void red_release(unsigned* p, unsigned v) {
    asm volatile("red.add.release.gpu.global.u32 [%0], %1;" :: "l"(p), "r"(v) : "memory");
}

// ---------------- MUFU-free activations ----------------
__device__ __forceinline__ float fast_rcp(float q) {
    float r = __uint_as_float(0x7EF311C2u - __float_as_uint(q));
    r = r * (2.0f - q * r);
    r = r * (2.0f - q * r);
    r = r * (2.0f - q * r);
    return r;
}
__device__ __forceinline__ float fast_tanh(float x) {
    x = fminf(fmaxf(x, -7.90531110763549805f), 7.90531110763549805f);
    float s = x * x;
    float p = fmaf(s, -2.76076847742355e-16f, 2.00018790482477e-13f);
    p = fmaf(p, s, -8.60467152213735e-11f);
    p = fmaf(p, s,  5.12229709037114e-08f);
    p = fmaf(p, s,  1.48572235717979e-05f);
    p = fmaf(p, s,  6.37261928875436e-04f);
    p = fmaf(p, s,  4.89352455891786e-03f);
    p = x * p;
    float q = fmaf(s, 1.19825839466702e-06f, 1.18534705686654e-04f);
    q = fmaf(q, s, 2.26843463243900e-03f);
    q = fmaf(q, s, 4.89352518554385e-03f);
    return p * fast_rcp(q);
}
__device__ __forceinline__ float fast_sigmoid(float x) {
    return fmaf(fast_tanh(0.5f * x), 0.5f, 0.5f);
}

// ---------------- fused setup: init state + all fp16 converts ----------------
__global__ void setup_kernel(const float* __restrict__ x,
                             const float* __restrict__ Wih,
                             const float* __restrict__ Whh) {
    const size_t stride = (size_t)gridDim.x * blockDim.x;
    const size_t t0 = (size_t)blockIdx.x * blockDim.x + threadIdx.x;

    for (size_t i = t0; i < 4 * 32; i += stride) g_ck[i] = 0u;
    for (size_t i = t0; i < (size_t)BATCH * HDIM; i += stride) {
        __half z = __float2half(0.f);
        g_hh[0][i] = z; g_hh[1][i] = z;
    }
    for (size_t i = t0; i < (size_t)G4 * IDIM; i += stride)
        g_Wihf[i] = __float2half(Wih[i]);
    // W_hh rearrange: out_row = blk*32 + g*8 + hl <- in_row = g*1024 + blk*8 + hl
    for (size_t i = t0; i < (size_t)G4 * HDIM; i += stride) {
        int out_row = (int)(i >> 10);
        int k   = (int)(i & 1023);
        int blk = out_row >> 5;
        int lg  = out_row & 31;
        int in_row = (lg >> 3) * HDIM + blk * 8 + (lg & 7);
        g_Wf[i] = __float2half(Whh[(size_t)in_row * HDIM + k]);
    }
    for (size_t i = t0; i < (size_t)M_TOTAL * IDIM; i += stride)
        g_xh[i] = __float2half(x[i]);
}

// ---------------- input projection GEMM (plain fp16 HMMA) ----------------
// xg[m][n] = x[m][:] . Wih[n][:] + bih[n]+bhh[n]; block 128x128, K-chunk 32.
#define GI_A     0
#define GI_B     10240
#define GI_STAGE 20480
#define GI_SMEM  (3*GI_STAGE)     // 61440

__global__ void __launch_bounds__(256, 1)
gemm_input_tc(const float* __restrict__ bih, const float* __restrict__ bhh) {
    extern __shared__ char smem[];
    const uint32_t sb = smem_u32(smem);
    const int tid = threadIdx.x, wid = tid >> 5, lane = tid & 31;
    const int mbase = blockIdx.x * 128;
    const int nbase = blockIdx.y * 128;
    const int wm = wid & 1, wn = wid >> 1;

    float acc[4][4][4] = {};

#define GI_ISSUE(i) do {                                                      \
    uint32_t st = sb + ((i) % 3) * GI_STAGE;                                  \
    _Pragma("unroll")                                                         \
    for (int p = 0; p < 2; p++) {                                             \
        int u = tid + p * 256; int r = u >> 2, c = u & 3;                     \
        size_t g = (size_t)(mbase + r) * IDIM + (size_t)(i) * 32 + c * 8;     \
        cp16(st + GI_A + r * 80 + c * 16, g_xh + g);                          \
    }                                                                         \
    _Pragma("unroll")                                                         \
    for (int p = 0; p < 2; p++) {                                             \
        int u = tid + p * 256; int r = u >> 2, c = u & 3;                     \
        size_t g = (size_t)(nbase + r) * IDIM + (size_t)(i) * 32 + c * 8;     \
        cp16(st + GI_B + r * 80 + c * 16, g_Wihf + g);                        \
    }                                                                         \
} while (0)

    GI_ISSUE(0); CP_COMMIT();
    GI_ISSUE(1); CP_COMMIT();

    for (int i = 0; i < 32; i++) {
        CP_WAIT1();
        __syncthreads();
        if (i + 2 < 32) GI_ISSUE(i + 2);
        CP_COMMIT();

        uint32_t st = sb + (i % 3) * GI_STAGE;
#pragma unroll
        for (int kk = 0; kk < 2; kk++) {
            const int colb = kk * 16 + ((lane >> 4) << 3);
            uint32_t a[4][4], b[2][4];
#pragma unroll
            for (int mt = 0; mt < 4; mt++) {
                int row = wm * 64 + mt * 16 + (lane & 15);
                ldmx4(a[mt], st + GI_A + row * 80 + colb * 2);
            }
#pragma unroll
            for (int bt = 0; bt < 2; bt++) {
                int row = wn * 32 + bt * 16 + (lane & 15);
                ldmx4(b[bt], st + GI_B + row * 80 + colb * 2);
            }
#pragma unroll
            for (int mt = 0; mt < 4; mt++)
#pragma unroll
                for (int nt = 0; nt < 4; nt++) {
                    int bt = nt >> 1, ns = nt & 1;
                    mma_f16(acc[mt][nt], a[mt], b[bt][ns], b[bt][ns + 2]);
                }
        }
    }

#pragma unroll
    for (int mt = 0; mt < 4; mt++) {
        int m0 = mbase + wm * 64 + mt * 16 + (lane >> 2);
#pragma unroll
        for (int nt = 0; nt < 4; nt++) {
            int n = nbase + wn * 32 + nt * 8 + (lane & 3) * 2;
            float b0 = bih[n] + bhh[n];
            float b1 = bih[n + 1] + bhh[n + 1];
            __stcs((float2*)(g_xg + (size_t)m0 * G4 + n),
                   make_float2(acc[mt][nt][0] + b0, acc[mt][nt][1] + b1));
            __stcs((float2*)(g_xg + (size_t)(m0 + 8) * G4 + n),
                   make_float2(acc[mt][nt][2] + b0, acc[mt][nt][3] + b1));
        }
    }
}

// ---------------- persistent LSTM step kernel (R10 structure, verbatim) ----
// Grid 128, 512 threads. Block owns 32 W rows (4 gates x 8 hcols).
// W fp16 slice (66KB) resident; per step: one consolidated flag wait
// (tid<4, hot spin, target 32*t), 3-stage incremental h pipeline,
// block-level flag post (tid==0) right after the h-store sync.
#define PS_W      0
#define PS_WCH    16896                  // 32 rows * 528B per chunk
#define PS_H      67584                  // 4 * PS_WCH
#define PS_HSTAGE 33792                  // 64 rows * 528B
#define PS_SG     (PS_H + 3*PS_HSTAGE)   // 168960 (dedicated gate-exchange)
#define PS_SMEM   (PS_SG + 4*2176*4)     // 203776

__global__ void __launch_bounds__(512, 1)
lstm_persistent(float* __restrict__ Hout, float* __restrict__ Cout) {
    extern __shared__ char smem[];
    const uint32_t sb = smem_u32(smem);
    const int tid = threadIdx.x, wid = tid >> 5, lane = tid & 31;
    const int blk = blockIdx.x;
    const int wm = wid & 1;            // M half (16 rows)
    const int wn = (wid >> 1) & 1;     // N half (32 batches)
    const int kw = wid >> 2;           // K quarter of chunk (64)
    const int myck = blk >> 5;         // chunk this block produces

    // ---- preload W slice fp16: 4 chunks x 32 rows x 256 k ----
#pragma unroll
    for (int p = 0; p < 8; p++) {
        int u = tid + p * 512;
        int ch = u >> 10, r = (u >> 5) & 31, c = u & 31;
        size_t g = (size_t)(blk * 32 + r) * HDIM + ch * 256 + c * 8;
        cp16(sb + PS_W + ch * PS_WCH + r * 528 + c * 16, g_Wf + g);
    }
    CP_COMMIT();
    CP_WAIT0();
    __syncthreads();

    float* sg = (float*)(smem + PS_SG);   // [4 kw][32 rows][68], dedicated

    const int hl = tid & 7;
    const int bcell = tid >> 3;
    const int hcol = blk * 8 + hl;
    float creg = 0.f;

    float xgi, xgf, xgg, xgo;
    {
        size_t xb = ((size_t)bcell * SEQ + 0) * G4 + hcol;
        xgi = __ldcs(g_xg + xb);
        xgf = __ldcs(g_xg + xb + 1024);
        xgg = __ldcs(g_xg + xb + 2048);
        xgo = __ldcs(g_xg + xb + 3072);
    }

    for (int t = 0; t < SEQ; t++) {
        const int pin = t & 1, pout = pin ^ 1;
        const __half* hhp = g_hh[pin];

        // ---- consolidated flag wait: all 4 chunks ready before pipeline ----
        if (tid < 4) {
            const unsigned tgt = 32u * (unsigned)t;
            const unsigned* fp = &g_ck[tid * 32];
            while (ld_acq(fp) < tgt) {}
        }
        __syncthreads();

        float acc[4][4] = {};

#define PS_ISSUE(i) do {                                                     \
    uint32_t st = sb + PS_H + ((i) % 3) * PS_HSTAGE;                         \
    _Pragma("unroll")                                                        \
    for (int p = 0; p < 4; p++) {                                            \
        int u = tid + p * 512; int r = u >> 5, c = u & 31;                   \
        size_t g = (size_t)r * HDIM + (size_t)(i) * 256 + c * 8;             \
        cp16(st + r * 528 + c * 16, hhp + g);                                \
    }                                                                        \
} while (0)

        PS_ISSUE(0); CP_COMMIT();
        PS_ISSUE(1); CP_COMMIT();

        for (int i = 0; i < 4; i++) {
            CP_WAIT1();
            __syncthreads();
            if (i + 2 < 4) PS_ISSUE(i + 2);
            CP_COMMIT();

            uint32_t hstg  = sb + PS_H + (i % 3) * PS_HSTAGE;
            uint32_t wbase = sb + PS_W + i * PS_WCH;

            uint32_t b[2][4][4];   // [nb(16 batches)][kk(k16)]
#pragma unroll
            for (int nb = 0; nb < 2; nb++)
#pragma unroll
                for (int kk = 0; kk < 4; kk++)
                    ldmx4(b[nb][kk],
                          hstg + (wn * 32 + nb * 16 + (lane & 15)) * 528
                               + (kw * 64 + kk * 16 + (lane >> 4) * 8) * 2);
#pragma unroll
            for (int kk = 0; kk < 4; kk++) {
                uint32_t a[4];
                ldmx4(a, wbase + (wm * 16 + (lane & 15)) * 528
                              + (kw * 64 + kk * 16 + (lane >> 4) * 8) * 2);
#pragma unroll
                for (int nb = 0; nb < 2; nb++)
#pragma unroll
                    for (int ns = 0; ns < 2; ns++)
                        mma_f16(acc[nb * 2 + ns], a, b[nb][kk][ns], b[nb][kk][ns + 2]);
            }
        }

        // gate exchange (dedicated sg: no WAR with stages)
        {
            int row = wm * 16 + (lane >> 2);
            float* base = sg + kw * 2176;
#pragma unroll
            for (int nb = 0; nb < 2; nb++)
#pragma unroll
                for (int ns = 0; ns < 2; ns++) {
                    int ai = nb * 2 + ns;
                    int col = wn * 32 + nb * 16 + ns * 8 + (lane & 3) * 2;
                    base[row * 68 + col]           = acc[ai][0];
                    base[row * 68 + col + 1]       = acc[ai][1];
                    base[(row + 8) * 68 + col]     = acc[ai][2];
                    base[(row + 8) * 68 + col + 1] = acc[ai][3];
                }
        }
        __syncthreads();

        // cell update (1 cell/thread, c in register); sum 4 kw partials
        float hnew, cnew;
        {
            float gi = xgi, gf = xgf, gg = xgg, go = xgo;
#pragma unroll
            for (int k = 0; k < 4; k++) {
                const float* base = sg + k * 2176;
                gi += base[(0 * 8 + hl) * 68 + bcell];
                gf += base[(1 * 8 + hl) * 68 + bcell];
                gg += base[(2 * 8 + hl) * 68 + bcell];
                go += base[(3 * 8 + hl) * 68 + bcell];
            }

            float iv = fast_sigmoid(gi);
            float fv = fast_sigmoid(gf);
            float gv = fast_tanh(gg);
            float ov = fast_sigmoid(go);

            cnew = fv * creg + iv * gv;
            hnew = ov * fast_tanh(cnew);
            creg = cnew;

            g_hh[pout][bcell * HDIM + hcol] = __float2half(hnew);
        }
        __syncthreads();           // all h stores + sg reads complete

        // post flag FIRST (wakes consumers), then outputs + prefetch
        if (tid == 0 && t + 1 < SEQ) red_release(&g_ck[myck * 32], 1u);

        size_t oidx = ((size_t)bcell * SEQ + t) * HDIM + hcol;
        __stcs(Hout + oidx, hnew);
        __stcs(Cout + oidx, cnew);

        if (t + 1 < SEQ) {
            size_t xb = ((size_t)bcell * SEQ + (t + 1)) * G4 + hcol;
            xgi = __ldcs(g_xg + xb);
            xgf = __ldcs(g_xg + xb + 1024);
            xgg = __ldcs(g_xg + xb + 2048);
            xgo = __ldcs(g_xg + xb + 3072);
        }
    }
}

// ---------------- launch ----------------
extern "C" void kernel_launch(void* const* d_in, const int* in_sizes, int n_in,
                              void* d_out, int out_size) {
    const float* x    = (const float*)d_in[0];
    const float* Wih  = (const float*)d_in[1];
    const float* Whh  = (const float*)d_in[2];
    const float* bih  = (const float*)d_in[3];
    const float* bhh  = (const float*)d_in[4];

    float* Hout = (float*)d_out;
    float* Cout = Hout + (size_t)BATCH * SEQ * HDIM;

    cudaFuncSetAttribute(gemm_input_tc,   cudaFuncAttributeMaxDynamicSharedMemorySize, GI_SMEM);
    cudaFuncSetAttribute(lstm_persistent, cudaFuncAttributeMaxDynamicSharedMemorySize, PS_SMEM);

    setup_kernel<<<1184, 256>>>(x, Wih, Whh);

    dim3 g1(M_TOTAL / 128, G4 / 128);   // 256 x 32
    gemm_input_tc<<<g1, 256, GI_SMEM>>>(bih, bhh);

    lstm_persistent<<<128, 512, PS_SMEM>>>(Hout, Cout);
}